// round 15
// baseline (speedup 1.0000x reference)
#include <cuda_runtime.h>
#include <cuda_fp16.h>
#include <cstdint>

// ----------------------------------------------------------------------------
// BitLinear: y = RMSNorm(x) @ w_q^T * gamma
// R1: harness PTX is baseline sm_103 (no 'a') -> no tcgen05.
// R13 (BEST 549us): fp16 HMMA 64x64 warp tiles, 128-thr CTAs, occ2, merged
//     prepass. GEMM 505us, tensor 89.6% (~5% off practical floor).
// FAILED experiments: R10/R11 persistence (ALU/regs), R12 legacy IMMA
//     (deprecated pipe, 3568us), R14 manual LDSM/HMMA interleave (576us --
//     asm volatile ordering constrained ptxas's scheduler).
// R15: R13 verbatim + remove dead final-kt wait/sync/load (strictly less work,
//     no reordering). Convergence point.
// ----------------------------------------------------------------------------

#define DIN   4096
#define DOUT  4096
#define MROWS 8192

__device__ __align__(256) __half g_xn[(size_t)MROWS * DIN];
__device__ __align__(256) __half g_wq[(size_t)DOUT * DIN];

// ---------------------------- PTX helpers -----------------------------------
__device__ __forceinline__ uint32_t smem_u32(const void* p) {
    uint32_t a;
    asm("{ .reg .u64 t; cvta.to.shared.u64 t, %1; cvt.u32.u64 %0, t; }"
        : "=r"(a) : "l"(p));
    return a;
}

__device__ __forceinline__ void cp_async16(uint32_t dst, const void* src) {
    asm volatile("cp.async.cg.shared.global [%0], [%1], 16;"
                 :: "r"(dst), "l"(src));
}

#define CP_COMMIT() asm volatile("cp.async.commit_group;" ::: "memory")

#define LDSM_X4(r0, r1, r2, r3, addr) \
    asm volatile("ldmatrix.sync.aligned.m8n8.x4.shared.b16 {%0,%1,%2,%3}, [%4];" \
                 : "=r"(r0), "=r"(r1), "=r"(r2), "=r"(r3) : "r"(addr))

#define MMA16816(d, a, b0, b1) \
    asm volatile("mma.sync.aligned.m16n8k16.row.col.f32.f16.f16.f32 " \
                 "{%0,%1,%2,%3}, {%4,%5,%6,%7}, {%8,%9}, {%0,%1,%2,%3};" \
                 : "+f"((d)[0]), "+f"((d)[1]), "+f"((d)[2]), "+f"((d)[3]) \
                 : "r"((a)[0]), "r"((a)[1]), "r"((a)[2]), "r"((a)[3]), \
                   "r"(b0), "r"(b1))

// ----------------------------- GEMM config ----------------------------------
constexpr int BM = 128, BN = 128, BK = 64;
constexpr int KTILES = DIN / BK;               // 64
constexpr int STAGES = 3;
constexpr int TILE_B  = BM * BK * 2;           // 16384 B per fp16 tile
constexpr int STAGE_B = 2 * TILE_B;            // A + B = 32768
constexpr int SMEM_SZ = STAGES * STAGE_B;      // 98304 (2 CTAs/SM)
constexpr int NTHREADS = 128;                  // 4 warps, warp tile 64x64

// --------------- Kernel 1: merged prepass (rmsnorm + wconv) ------------------
// blocks [0, MROWS): RMSNorm row -> fp16 xn
// blocks [MROWS, MROWS+4096): w_q fp32 -> fp16
__global__ __launch_bounds__(256) void prepass_kernel(
    const float* __restrict__ x, const float* __restrict__ nw,
    const float* __restrict__ wq) {
    const int b = blockIdx.x;
    const int t = threadIdx.x;

    if (b < MROWS) {
        const int row = b;
        const float4* xr = reinterpret_cast<const float4*>(x) + (size_t)row * (DIN / 4);
        const float4* nw4 = reinterpret_cast<const float4*>(nw);

        float4 v[4];
        float ss = 0.f;
#pragma unroll
        for (int i = 0; i < 4; i++) {
            v[i] = xr[t + i * 256];
            ss += v[i].x * v[i].x + v[i].y * v[i].y + v[i].z * v[i].z + v[i].w * v[i].w;
        }
#pragma unroll
        for (int o = 16; o > 0; o >>= 1) ss += __shfl_xor_sync(0xffffffffu, ss, o);

        __shared__ float wss[8];
        __shared__ float s_scale;
        if ((t & 31) == 0) wss[t >> 5] = ss;
        __syncthreads();
        if (t == 0) {
            float tot = 0.f;
#pragma unroll
            for (int i = 0; i < 8; i++) tot += wss[i];
            s_scale = rsqrtf(tot * (1.0f / DIN) + 1e-6f);
        }
        __syncthreads();
        const float sc = s_scale;

        uint2* xo = reinterpret_cast<uint2*>(g_xn + (size_t)row * DIN);
#pragma unroll
        for (int i = 0; i < 4; i++) {
            float4 w = nw4[t + i * 256];
            __half2 h01 = __floats2half2_rn(v[i].x * sc * w.x, v[i].y * sc * w.y);
            __half2 h23 = __floats2half2_rn(v[i].z * sc * w.z, v[i].w * sc * w.w);
            uint2 u;
            u.x = *reinterpret_cast<uint32_t*>(&h01);
            u.y = *reinterpret_cast<uint32_t*>(&h23);
            xo[t + i * 256] = u;
        }
    } else {
        const size_t gid = (size_t)(b - MROWS) * 256 + t;
        const float4* w4 = reinterpret_cast<const float4*>(wq);
        uint2* o = reinterpret_cast<uint2*>(g_wq);
#pragma unroll
        for (int i = 0; i < 4; i++) {
            size_t idx = gid + (size_t)i * 1048576;
            float4 v = w4[idx];
            __half2 h01 = __floats2half2_rn(v.x, v.y);
            __half2 h23 = __floats2half2_rn(v.z, v.w);
            uint2 u;
            u.x = *reinterpret_cast<uint32_t*>(&h01);
            u.y = *reinterpret_cast<uint32_t*>(&h23);
            o[idx] = u;
        }
    }
}

// ------------------------ Kernel 2: HMMA GEMM (R13) --------------------------
// 128 threads = 4 warps, 2(m) x 2(n), warp tile 64x64; 2 CTAs/SM.
// Fragments one kk-step ahead (double-buffered); barrier after kk3 HMMAs;
// final-kt tail work elided.
__global__ __launch_bounds__(NTHREADS, 2)
void bitlinear_gemm_kernel(const float* __restrict__ gamma, float* __restrict__ out) {
    extern __shared__ char smem[];
    const uint32_t sb = smem_u32(smem);
    const int tid = threadIdx.x;
    const int wid = tid >> 5;
    const int lane = tid & 31;
    const int warp_m = wid >> 1;       // 0..1
    const int warp_n = wid & 1;        // 0..1
    const int m0 = blockIdx.y * BM;
    const int n0 = blockIdx.x * BN;

    // ---- per-thread copy geometry: 1024 chunks/tile, 128 thr -> 8 each
    const int cc = tid & 7;
    const int r0c = tid >> 3;          // 0..15; r&7 invariant under +16
    const uint32_t so_base = (uint32_t)(r0c * 128 + ((cc ^ (r0c & 7)) << 4));
    const char* gA = (const char*)g_xn + (size_t)(m0 + r0c) * (DIN * 2) + cc * 16;
    const char* gB = (const char*)g_wq + (size_t)(n0 + r0c) * (DIN * 2) + cc * 16;

    auto issue_stage = [&](int s, int kt) {
        const uint32_t sdst = sb + (uint32_t)s * STAGE_B + so_base;
        const uint32_t koff = (uint32_t)kt * 128;
#pragma unroll
        for (int i = 0; i < 8; i++)
            cp_async16(sdst + i * (16 * 128),
                       gA + koff + (size_t)i * (16 * DIN * 2));
#pragma unroll
        for (int i = 0; i < 8; i++)
            cp_async16(sdst + TILE_B + i * (16 * 128),
                       gB + koff + (size_t)i * (16 * DIN * 2));
    };

    // ---- ldmatrix base offsets (kk=0); off(kk) = off0 ^ (kk << 5)
    const int rA0 = warp_m * 64 + (lane & 15);
    const int cgA = lane >> 4;
    const int gB4 = lane >> 3;
    const int rB0 = warp_n * 64 + ((gB4 & 2) << 2) + (lane & 7);
    const int cgB = gB4 & 1;

    uint32_t offA0[4], offB0[4];
#pragma unroll
    for (int mi = 0; mi < 4; mi++) {
        const int r = rA0 + mi * 16;
        offA0[mi] = (uint32_t)(r * 128 + ((cgA ^ (r & 7)) << 4));
    }
#pragma unroll
    for (int p = 0; p < 4; p++) {
        const int r = rB0 + p * 16;
        offB0[p] = (uint32_t)(r * 128 + ((cgB ^ (r & 7)) << 4)) + TILE_B;
    }

    float acc[4][8][4];
#pragma unroll
    for (int mi = 0; mi < 4; mi++)
#pragma unroll
        for (int nj = 0; nj < 8; nj++)
#pragma unroll
            for (int e = 0; e < 4; e++) acc[mi][nj][e] = 0.f;

    uint32_t af[2][4][4], bf[2][4][4];   // [buf][frag][reg]

    auto load_frags = [&](int buf, uint32_t base, int kk) {
        const uint32_t kx = (uint32_t)(kk << 5);
#pragma unroll
        for (int mi = 0; mi < 4; mi++)
            LDSM_X4(af[buf][mi][0], af[buf][mi][1], af[buf][mi][2],
                    af[buf][mi][3], base + (offA0[mi] ^ kx));
#pragma unroll
        for (int p = 0; p < 4; p++)
            LDSM_X4(bf[buf][p][0], bf[buf][p][1], bf[buf][p][2],
                    bf[buf][p][3], base + (offB0[p] ^ kx));
    };

    auto do_mma = [&](int buf) {
#pragma unroll
        for (int mi = 0; mi < 4; mi++)
#pragma unroll
            for (int p = 0; p < 4; p++) {
                MMA16816(acc[mi][2 * p],     af[buf][mi], bf[buf][p][0], bf[buf][p][1]);
                MMA16816(acc[mi][2 * p + 1], af[buf][mi], bf[buf][p][2], bf[buf][p][3]);
            }
    };

    // ---- prologue: fill 2 stages, publish stage 0, prefetch its kk0 frags
    issue_stage(0, 0); CP_COMMIT();
    issue_stage(1, 1); CP_COMMIT();
    asm volatile("cp.async.wait_group 1;" ::: "memory");
    __syncthreads();
    load_frags(0, sb, 0);

    // ---- main loop: frags always one kk ahead; barrier after kk3 HMMAs
    int stage = 0;
    for (int kt = 0; kt < KTILES; kt++) {
        const uint32_t base = sb + (uint32_t)stage * STAGE_B;

        if (kt + 2 < KTILES) {
            int ns = stage + 2; if (ns >= STAGES) ns -= STAGES;
            issue_stage(ns, kt + 2);
        }
        CP_COMMIT();

#pragma unroll
        for (int kk = 0; kk < 3; kk++) {
            load_frags((kk + 1) & 1, base, kk + 1);
            do_mma(kk & 1);
        }
        do_mma(1);   // kk=3 (frags loaded at kk=2 into buf 1)

        if (kt + 1 < KTILES) {       // skip dead tail on final kt
            asm volatile("cp.async.wait_group 1;" ::: "memory");
            __syncthreads();
            int nstage = stage + 1; if (nstage >= STAGES) nstage -= STAGES;
            load_frags(0, sb + (uint32_t)nstage * STAGE_B, 0);
            stage = nstage;
        }
    }

    // ---- epilogue: *gamma, write f32
    const int col_l = (lane & 3) * 2;
    const float* gptr = gamma + n0 + warp_n * 64;
    float gv0[8], gv1[8];
#pragma unroll
    for (int nj = 0; nj < 8; nj++) {
        gv0[nj] = __ldg(gptr + nj * 8 + col_l);
        gv1[nj] = __ldg(gptr + nj * 8 + col_l + 1);
    }

    const int row_base = m0 + warp_m * 64 + (lane >> 2);
#pragma unroll
    for (int mi = 0; mi < 4; mi++) {
        float* op0 = out + (size_t)(row_base + mi * 16) * DOUT + n0 + warp_n * 64;
        float* op1 = op0 + (size_t)8 * DOUT;
#pragma unroll
        for (int nj = 0; nj < 8; nj++) {
            float2 v0, v1;
            v0.x = acc[mi][nj][0] * gv0[nj];
            v0.y = acc[mi][nj][1] * gv1[nj];
            v1.x = acc[mi][nj][2] * gv0[nj];
            v1.y = acc[mi][nj][3] * gv1[nj];
            *reinterpret_cast<float2*>(op0 + nj * 8 + col_l) = v0;
            *reinterpret_cast<float2*>(op1 + nj * 8 + col_l) = v1;
        }
    }
}

// ------------------------------- launch --------------------------------------
extern "C" void kernel_launch(void* const* d_in, const int* in_sizes, int n_in,
                              void* d_out, int out_size) {
    const float* x     = (const float*)d_in[0];  // [2,4096,4096]
    const float* nw    = (const float*)d_in[1];  // [4096]
    const float* wq    = (const float*)d_in[2];  // [4096,4096]
    const float* gamma = (const float*)d_in[3];  // [4096]
    float* out = (float*)d_out;

    cudaFuncSetAttribute(bitlinear_gemm_kernel,
                         cudaFuncAttributeMaxDynamicSharedMemorySize, SMEM_SZ);

    prepass_kernel<<<MROWS + 4096, 256>>>(x, nw, wq);
    bitlinear_gemm_kernel<<<dim3(DOUT / BN, MROWS / BM), NTHREADS, SMEM_SZ>>>(gamma, out);
}

// round 16
// speedup vs baseline: 1.0654x; 1.0654x over previous
#include <cuda_runtime.h>
#include <cuda_fp16.h>
#include <cstdint>

// ----------------------------------------------------------------------------
// BitLinear: y = RMSNorm(x) @ w_q^T * gamma
// R1: harness PTX is baseline sm_103 (no 'a') -> no tcgen05.
// R13 (BEST 549us): fp16 HMMA 64x64 warp tiles, 128-thr CTAs, occ2, merged
//     prepass. GEMM 505us, tensor 89.6% (~9% above hard floor 455+44us).
// FAILED experiments (all regressed): R10/R11 persistence (ALU/regs),
//     R12 legacy IMMA (deprecated pipe, 3568us), R14 manual LDSM/HMMA
//     interleave (576us), R15 conditional barrier in loop tail (586us).
// R16: EXACT revert to R13. The R13 loop shape (unconditional wait/sync,
//     guarded issue/load only) is the ptxas-scheduling local optimum.
// ----------------------------------------------------------------------------

#define DIN   4096
#define DOUT  4096
#define MROWS 8192

__device__ __align__(256) __half g_xn[(size_t)MROWS * DIN];
__device__ __align__(256) __half g_wq[(size_t)DOUT * DIN];

// ---------------------------- PTX helpers -----------------------------------
__device__ __forceinline__ uint32_t smem_u32(const void* p) {
    uint32_t a;
    asm("{ .reg .u64 t; cvta.to.shared.u64 t, %1; cvt.u32.u64 %0, t; }"
        : "=r"(a) : "l"(p));
    return a;
}

__device__ __forceinline__ void cp_async16(uint32_t dst, const void* src) {
    asm volatile("cp.async.cg.shared.global [%0], [%1], 16;"
                 :: "r"(dst), "l"(src));
}

#define CP_COMMIT() asm volatile("cp.async.commit_group;" ::: "memory")

#define LDSM_X4(r0, r1, r2, r3, addr) \
    asm volatile("ldmatrix.sync.aligned.m8n8.x4.shared.b16 {%0,%1,%2,%3}, [%4];" \
                 : "=r"(r0), "=r"(r1), "=r"(r2), "=r"(r3) : "r"(addr))

#define MMA16816(d, a, b0, b1) \
    asm volatile("mma.sync.aligned.m16n8k16.row.col.f32.f16.f16.f32 " \
                 "{%0,%1,%2,%3}, {%4,%5,%6,%7}, {%8,%9}, {%0,%1,%2,%3};" \
                 : "+f"((d)[0]), "+f"((d)[1]), "+f"((d)[2]), "+f"((d)[3]) \
                 : "r"((a)[0]), "r"((a)[1]), "r"((a)[2]), "r"((a)[3]), \
                   "r"(b0), "r"(b1))

// ----------------------------- GEMM config ----------------------------------
constexpr int BM = 128, BN = 128, BK = 64;
constexpr int KTILES = DIN / BK;               // 64
constexpr int STAGES = 3;
constexpr int TILE_B  = BM * BK * 2;           // 16384 B per fp16 tile
constexpr int STAGE_B = 2 * TILE_B;            // A + B = 32768
constexpr int SMEM_SZ = STAGES * STAGE_B;      // 98304 (2 CTAs/SM)
constexpr int NTHREADS = 128;                  // 4 warps, warp tile 64x64

// --------------- Kernel 1: merged prepass (rmsnorm + wconv) ------------------
// blocks [0, MROWS): RMSNorm row -> fp16 xn
// blocks [MROWS, MROWS+4096): w_q fp32 -> fp16 (4096 elems per block)
__global__ __launch_bounds__(256) void prepass_kernel(
    const float* __restrict__ x, const float* __restrict__ nw,
    const float* __restrict__ wq) {
    const int b = blockIdx.x;
    const int t = threadIdx.x;

    if (b < MROWS) {
        // ---------------- RMSNorm -> fp16 ----------------
        const int row = b;
        const float4* xr = reinterpret_cast<const float4*>(x) + (size_t)row * (DIN / 4);
        const float4* nw4 = reinterpret_cast<const float4*>(nw);

        float4 v[4];
        float ss = 0.f;
#pragma unroll
        for (int i = 0; i < 4; i++) {
            v[i] = xr[t + i * 256];
            ss += v[i].x * v[i].x + v[i].y * v[i].y + v[i].z * v[i].z + v[i].w * v[i].w;
        }
#pragma unroll
        for (int o = 16; o > 0; o >>= 1) ss += __shfl_xor_sync(0xffffffffu, ss, o);

        __shared__ float wss[8];
        __shared__ float s_scale;
        if ((t & 31) == 0) wss[t >> 5] = ss;
        __syncthreads();
        if (t == 0) {
            float tot = 0.f;
#pragma unroll
            for (int i = 0; i < 8; i++) tot += wss[i];
            s_scale = rsqrtf(tot * (1.0f / DIN) + 1e-6f);
        }
        __syncthreads();
        const float sc = s_scale;

        uint2* xo = reinterpret_cast<uint2*>(g_xn + (size_t)row * DIN);
#pragma unroll
        for (int i = 0; i < 4; i++) {
            float4 w = nw4[t + i * 256];
            __half2 h01 = __floats2half2_rn(v[i].x * sc * w.x, v[i].y * sc * w.y);
            __half2 h23 = __floats2half2_rn(v[i].z * sc * w.z, v[i].w * sc * w.w);
            uint2 u;
            u.x = *reinterpret_cast<uint32_t*>(&h01);
            u.y = *reinterpret_cast<uint32_t*>(&h23);
            xo[t + i * 256] = u;
        }
    } else {
        // ---------------- w_q fp32 -> fp16 ----------------
        const size_t gid = (size_t)(b - MROWS) * 256 + t;     // 1,048,576 total
        const float4* w4 = reinterpret_cast<const float4*>(wq);
        uint2* o = reinterpret_cast<uint2*>(g_wq);
#pragma unroll
        for (int i = 0; i < 4; i++) {
            size_t idx = gid + (size_t)i * 1048576;
            float4 v = w4[idx];
            __half2 h01 = __floats2half2_rn(v.x, v.y);
            __half2 h23 = __floats2half2_rn(v.z, v.w);
            uint2 u;
            u.x = *reinterpret_cast<uint32_t*>(&h01);
            u.y = *reinterpret_cast<uint32_t*>(&h23);
            o[idx] = u;
        }
    }
}

// ------------------------ Kernel 2: HMMA GEMM (R13) --------------------------
// 128 threads = 4 warps, 2(m) x 2(n), warp tile 64x64; 2 CTAs/SM.
// All fragments one kk-step ahead; barrier after kk3 HMMAs.
__global__ __launch_bounds__(NTHREADS, 2)
void bitlinear_gemm_kernel(const float* __restrict__ gamma, float* __restrict__ out) {
    extern __shared__ char smem[];
    const uint32_t sb = smem_u32(smem);
    const int tid = threadIdx.x;
    const int wid = tid >> 5;
    const int lane = tid & 31;
    const int warp_m = wid >> 1;       // 0..1
    const int warp_n = wid & 1;        // 0..1
    const int m0 = blockIdx.y * BM;
    const int n0 = blockIdx.x * BN;

    // ---- per-thread copy geometry: 1024 chunks/tile, 128 thr -> 8 each
    const int cc = tid & 7;
    const int r0c = tid >> 3;          // 0..15; r&7 invariant under +16
    const uint32_t so_base = (uint32_t)(r0c * 128 + ((cc ^ (r0c & 7)) << 4));
    const char* gA = (const char*)g_xn + (size_t)(m0 + r0c) * (DIN * 2) + cc * 16;
    const char* gB = (const char*)g_wq + (size_t)(n0 + r0c) * (DIN * 2) + cc * 16;

    auto issue_stage = [&](int s, int kt) {
        const uint32_t sdst = sb + (uint32_t)s * STAGE_B + so_base;
        const uint32_t koff = (uint32_t)kt * 128;
#pragma unroll
        for (int i = 0; i < 8; i++)
            cp_async16(sdst + i * (16 * 128),
                       gA + koff + (size_t)i * (16 * DIN * 2));
#pragma unroll
        for (int i = 0; i < 8; i++)
            cp_async16(sdst + TILE_B + i * (16 * 128),
                       gB + koff + (size_t)i * (16 * DIN * 2));
    };

    // ---- ldmatrix base offsets (kk=0); off(kk) = off0 ^ (kk << 5)
    const int rA0 = warp_m * 64 + (lane & 15);
    const int cgA = lane >> 4;
    const int gB4 = lane >> 3;
    const int rB0 = warp_n * 64 + ((gB4 & 2) << 2) + (lane & 7);
    const int cgB = gB4 & 1;

    uint32_t offA0[4], offB0[4];
#pragma unroll
    for (int mi = 0; mi < 4; mi++) {
        const int r = rA0 + mi * 16;
        offA0[mi] = (uint32_t)(r * 128 + ((cgA ^ (r & 7)) << 4));
    }
#pragma unroll
    for (int p = 0; p < 4; p++) {
        const int r = rB0 + p * 16;
        offB0[p] = (uint32_t)(r * 128 + ((cgB ^ (r & 7)) << 4)) + TILE_B;
    }

    float acc[4][8][4];
#pragma unroll
    for (int mi = 0; mi < 4; mi++)
#pragma unroll
        for (int nj = 0; nj < 8; nj++)
#pragma unroll
            for (int e = 0; e < 4; e++) acc[mi][nj][e] = 0.f;

    uint32_t af[2][4][4], bf[2][4][4];   // [buf][frag][reg]

    auto load_frags = [&](int buf, uint32_t base, int kk) {
        const uint32_t kx = (uint32_t)(kk << 5);
#pragma unroll
        for (int mi = 0; mi < 4; mi++)
            LDSM_X4(af[buf][mi][0], af[buf][mi][1], af[buf][mi][2],
                    af[buf][mi][3], base + (offA0[mi] ^ kx));
#pragma unroll
        for (int p = 0; p < 4; p++)
            LDSM_X4(bf[buf][p][0], bf[buf][p][1], bf[buf][p][2],
                    bf[buf][p][3], base + (offB0[p] ^ kx));
    };

    auto do_mma = [&](int buf) {
#pragma unroll
        for (int mi = 0; mi < 4; mi++)
#pragma unroll
            for (int p = 0; p < 4; p++) {
                MMA16816(acc[mi][2 * p],     af[buf][mi], bf[buf][p][0], bf[buf][p][1]);
                MMA16816(acc[mi][2 * p + 1], af[buf][mi], bf[buf][p][2], bf[buf][p][3]);
            }
    };

    // ---- prologue: fill 2 stages, publish stage 0, prefetch its kk0 frags
    issue_stage(0, 0); CP_COMMIT();
    issue_stage(1, 1); CP_COMMIT();
    asm volatile("cp.async.wait_group 1;" ::: "memory");
    __syncthreads();
    load_frags(0, sb, 0);

    // ---- main loop: frags always one kk ahead; barrier after kk3 HMMAs
    int stage = 0;
    for (int kt = 0; kt < KTILES; kt++) {
        const uint32_t base = sb + (uint32_t)stage * STAGE_B;

        if (kt + 2 < KTILES) {
            int ns = stage + 2; if (ns >= STAGES) ns -= STAGES;
            issue_stage(ns, kt + 2);
        }
        CP_COMMIT();

#pragma unroll
        for (int kk = 0; kk < 3; kk++) {
            load_frags((kk + 1) & 1, base, kk + 1);
            do_mma(kk & 1);
        }
        do_mma(1);   // kk=3 (frags loaded at kk=2 into buf 1)

        asm volatile("cp.async.wait_group 1;" ::: "memory");
        __syncthreads();

        int nstage = stage + 1; if (nstage >= STAGES) nstage -= STAGES;
        if (kt + 1 < KTILES)
            load_frags(0, sb + (uint32_t)nstage * STAGE_B, 0);
        stage = nstage;
    }

    // ---- epilogue: *gamma, write f32
    const int col_l = (lane & 3) * 2;
    const float* gptr = gamma + n0 + warp_n * 64;
    float gv0[8], gv1[8];
#pragma unroll
    for (int nj = 0; nj < 8; nj++) {
        gv0[nj] = __ldg(gptr + nj * 8 + col_l);
        gv1[nj] = __ldg(gptr + nj * 8 + col_l + 1);
    }

    const int row_base = m0 + warp_m * 64 + (lane >> 2);
#pragma unroll
    for (int mi = 0; mi < 4; mi++) {
        float* op0 = out + (size_t)(row_base + mi * 16) * DOUT + n0 + warp_n * 64;
        float* op1 = op0 + (size_t)8 * DOUT;
#pragma unroll
        for (int nj = 0; nj < 8; nj++) {
            float2 v0, v1;
            v0.x = acc[mi][nj][0] * gv0[nj];
            v0.y = acc[mi][nj][1] * gv1[nj];
            v1.x = acc[mi][nj][2] * gv0[nj];
            v1.y = acc[mi][nj][3] * gv1[nj];
            *reinterpret_cast<float2*>(op0 + nj * 8 + col_l) = v0;
            *reinterpret_cast<float2*>(op1 + nj * 8 + col_l) = v1;
        }
    }
}

// ------------------------------- launch --------------------------------------
extern "C" void kernel_launch(void* const* d_in, const int* in_sizes, int n_in,
                              void* d_out, int out_size) {
    const float* x     = (const float*)d_in[0];  // [2,4096,4096]
    const float* nw    = (const float*)d_in[1];  // [4096]
    const float* wq    = (const float*)d_in[2];  // [4096,4096]
    const float* gamma = (const float*)d_in[3];  // [4096]
    float* out = (float*)d_out;

    cudaFuncSetAttribute(bitlinear_gemm_kernel,
                         cudaFuncAttributeMaxDynamicSharedMemorySize, SMEM_SZ);

    prepass_kernel<<<MROWS + 4096, 256>>>(x, nw, wq);
    bitlinear_gemm_kernel<<<dim3(DOUT / BN, MROWS / BM), NTHREADS, SMEM_SZ>>>(gamma, out);
}